// round 5
// baseline (speedup 1.0000x reference)
#include <cuda_runtime.h>

#define T_STEPS 100
#define BATCH   256
#define D0      784
#define D1      1024
#define D2      256
#define XCAP    128

#define ALPHA 0.8f
#define BETA  0.95f
#define OMB   0.05f

// layer 1: 16 col-chunks of 64 cols (tile 785x64 fl = 200.96 KB), 5 row-groups -> 80 blocks
// layer 2:  8 col-chunks of 32 cols (tile 1025x32 fl = 131.2 KB), 8 row-groups -> 64 blocks
#define N_CH1 16
#define REP1  5
#define NB_L1 (N_CH1 * REP1)      // 80
#define N_CH2 8
#define REP2  8
#define NB_L2 (N_CH2 * REP2)      // 64
#define NBLOCKS (NB_L1 + NB_L2)   // 144  (<= 148 SMs, 1 block/SM -> co-resident)
#define NT 1024
#define SMEM_BYTES ((D0 + 1) * 64 * 4)   // 200960, covers both tile types

// ---------------- device scratch ----------------
__device__ float g_Wt1[(D0 + 1) * D1];              // [k][j], row D0 = zeros
__device__ float g_Wt2[(D1 + 1) * D2];              // [k][j], row D1 = zeros
__device__ unsigned short g_xidx[T_STEPS * BATCH * XCAP];
__device__ int g_xnnz[T_STEPS * BATCH];
__device__ unsigned g_s1mask[2][BATCH][32];         // double-buffered layer-1 spike bitmasks
__device__ unsigned g_count;
__device__ volatile unsigned g_gen;

// ---------------- prep kernels ----------------
__global__ void transpose_W1(const float* __restrict__ W1) {
    int idx = blockIdx.x * blockDim.x + threadIdx.x;
    if (idx < (D0 + 1) * D1) {
        int k = idx / D1, j = idx % D1;
        g_Wt1[idx] = (k < D0) ? W1[j * D0 + k] : 0.0f;
    }
}
__global__ void transpose_W2(const float* __restrict__ W2) {
    int idx = blockIdx.x * blockDim.x + threadIdx.x;
    if (idx < (D1 + 1) * D2) {
        int k = idx / D2, j = idx % D2;
        g_Wt2[idx] = (k < D1) ? W2[j * D1 + k] : 0.0f;
    }
}
// one warp per (t,b) row; ascending index compaction
__global__ void build_xidx(const float* __restrict__ x) {
    int row  = blockIdx.x * 8 + (threadIdx.x >> 5);
    int lane = threadIdx.x & 31;
    const float* xr = x + (size_t)row * D0;
    unsigned short* out = g_xidx + row * XCAP;
    int base = 0;
    #pragma unroll 1
    for (int c = 0; c < 25; ++c) {
        int i = c * 32 + lane;
        bool p = (i < D0) && (xr[i] != 0.0f);
        unsigned m = __ballot_sync(0xffffffffu, p);
        if (p) {
            int pos = base + __popc(m & ((1u << lane) - 1u));
            if (pos < XCAP) out[pos] = (unsigned short)i;
        }
        base += __popc(m);
    }
    if (lane == 0) {
        if (base > XCAP) base = XCAP;
        int nnzp = (base + 3) & ~3;
        if (nnzp > XCAP) nnzp = XCAP;
        for (int p = base; p < nnzp; ++p) out[p] = (unsigned short)D0;  // zero-row pad
        g_xnnz[row] = nnzp;
    }
}
__global__ void init_misc(float* __restrict__ out) {
    int i = blockIdx.x * blockDim.x + threadIdx.x;
    if (i < BATCH * D2) out[i] = 0.0f;                       // spikes[t=0] = 0
    if (i < BATCH * 32) ((unsigned*)g_s1mask)[i] = 0u;       // s1[t=0] = 0 (buf 0)
    if (i == 0) { g_count = 0; g_gen = 0; }
}

// ---------------- grid barrier (all 144 blocks co-resident) ----------------
__device__ __forceinline__ void grid_barrier(unsigned target) {
    __threadfence();
    __syncthreads();
    if (threadIdx.x == 0) {
        unsigned t = atomicAdd(&g_count, 1u);
        if (t == NBLOCKS - 1) {
            g_count = 0;
            __threadfence();
            g_gen = target;
        } else {
            while (g_gen < target) { }
            __threadfence();
        }
    }
    __syncthreads();
}

// bit-expand a 16-bit value to even bit positions of a 32-bit value
__device__ __forceinline__ unsigned expand16(unsigned v) {
    v &= 0xFFFFu;
    v = (v | (v << 8)) & 0x00FF00FFu;
    v = (v | (v << 4)) & 0x0F0F0F0Fu;
    v = (v | (v << 2)) & 0x33333333u;
    v = (v | (v << 1)) & 0x55555555u;
    return v;
}

// ---------------- persistent SNN kernel ----------------
__global__ void __launch_bounds__(NT, 1)
snn_persistent(float* __restrict__ out) {
    extern __shared__ float tile[];
    const unsigned FULL = 0xffffffffu;
    int tid  = threadIdx.x;
    int warp = tid >> 5;
    int lane = tid & 31;
    int bx   = blockIdx.x;

    if (bx < NB_L1) {
        // ===== layer 1: chunk of 64 cols in SMEM, warp = one batch row (x2 waves) =====
        int ch  = bx & (N_CH1 - 1);       // 0..15
        int rep = bx >> 4;                // 0..4
        int jb  = ch * 64;
        // load weight tile [785][64]
        for (int k = warp; k < D0 + 1; k += 32) {
            tile[k * 64 + lane]      = g_Wt1[k * D1 + jb + lane];
            tile[k * 64 + 32 + lane] = g_Wt1[k * D1 + jb + 32 + lane];
        }
        int r0 = (rep * BATCH) / REP1, r1 = ((rep + 1) * BATCH) / REP1;
        int rowA = r0 + warp;
        int rowB = r0 + 32 + warp;
        bool hasA = rowA < r1, hasB = rowB < r1;
        // lane owns cols jb+2*lane, jb+2*lane+1
        float2 Ia = {0.f, 0.f}, Va = {0.f, 0.f};
        float2 Ib = {0.f, 0.f}, Vb = {0.f, 0.f};
        __syncthreads();

        for (int t = 1; t < T_STEPS; ++t) {
            #pragma unroll 1
            for (int pass = 0; pass < 2; ++pass) {
                bool has = pass ? hasB : hasA;
                if (!has) continue;
                int row = pass ? rowB : rowA;
                float2 I = pass ? Ib : Ia;
                float2 V = pass ? Vb : Va;

                int xr = (t - 1) * BATCH + row;
                int nnzp = __ldg(&g_xnnz[xr]);
                const unsigned short* lst = g_xidx + xr * XCAP;
                int i0 = lst[lane], i1 = lst[32 + lane];
                int i2 = lst[64 + lane], i3 = lst[96 + lane];

                float2 acc = {0.f, 0.f};
                #define GRP(IR, OFF)                                            \
                {   int lim = nnzp - (OFF);                                     \
                    if (lim > 0) {                                              \
                        if (lim > 32) lim = 32;                                 \
                        for (int b = 0; b < lim; ++b) {                         \
                            int k = __shfl_sync(FULL, (IR), b);                 \
                            float2 wv = *(const float2*)(tile + k * 64 + lane * 2); \
                            acc.x += wv.x; acc.y += wv.y;                       \
                        }                                                       \
                    }                                                           \
                }
                GRP(i0, 0) GRP(i1, 32) GRP(i2, 64) GRP(i3, 96)
                #undef GRP

                I.x = ALPHA * I.x + acc.x;  I.y = ALPHA * I.y + acc.y;
                float2 Vp;
                Vp.x = BETA * V.x + OMB * I.x;  Vp.y = BETA * V.y + OMB * I.y;
                bool s0 = Vp.x > 1.0f, s1 = Vp.y > 1.0f;
                V.x = s0 ? 0.f : Vp.x;  V.y = s1 ? 0.f : Vp.y;

                unsigned be = __ballot_sync(FULL, s0);   // cols jb + 2*lane
                unsigned bo = __ballot_sync(FULL, s1);   // cols jb + 2*lane + 1
                if (lane == 0) {
                    unsigned w0 = expand16(be) | (expand16(bo) << 1);
                    unsigned w1 = expand16(be >> 16) | (expand16(bo >> 16) << 1);
                    unsigned long long pk = (unsigned long long)w0 |
                                            ((unsigned long long)w1 << 32);
                    *(unsigned long long*)&g_s1mask[t & 1][row][2 * ch] = pk;
                }
                if (pass) { Ib = I; Vb = V; } else { Ia = I; Va = V; }
            }
            if (t < T_STEPS - 1) grid_barrier((unsigned)t);
        }
    } else {
        // ===== layer 2: chunk of 32 cols in SMEM, warp = one batch row =====
        int bi  = bx - NB_L1;             // 0..63
        int ch  = bi & (N_CH2 - 1);       // 0..7
        int rep = bi >> 3;                // 0..7
        int jb  = ch * 32;
        for (int k = warp; k < D1 + 1; k += 32)
            tile[k * 32 + lane] = g_Wt2[k * D2 + jb + lane];
        int row = rep * 32 + warp;        // lane owns col jb + lane
        float I = 0.f, V = 0.f;
        __syncthreads();

        for (int t = 1; t < T_STEPS; ++t) {
            unsigned m = __ldcg(&g_s1mask[(t - 1) & 1][row][lane]);  // word 'lane'
            float acc = 0.f;
            #pragma unroll 1
            for (int w2 = 0; w2 < 32; ++w2) {
                unsigned bits = __shfl_sync(FULL, m, w2);
                while (bits) {
                    int b = __ffs(bits) - 1;
                    bits &= bits - 1;
                    acc += tile[(w2 * 32 + b) * 32 + lane];   // ascending k
                }
            }
            I = ALPHA * I + acc;
            float Vp = BETA * V + OMB * I;
            bool s = Vp > 1.0f;
            V = s ? 0.f : Vp;
            out[t * (BATCH * D2) + row * D2 + jb + lane] = s ? 1.0f : 0.0f;

            if (t < T_STEPS - 1) grid_barrier((unsigned)t);
        }
    }
}

// ---------------- launch ----------------
extern "C" void kernel_launch(void* const* d_in, const int* in_sizes, int n_in,
                              void* d_out, int out_size) {
    const float *x = nullptr, *W1 = nullptr, *W2 = nullptr;
    for (int i = 0; i < n_in; ++i) {
        if      (in_sizes[i] == T_STEPS * BATCH * D0) x  = (const float*)d_in[i];
        else if (in_sizes[i] == D1 * D0)              W1 = (const float*)d_in[i];
        else if (in_sizes[i] == D2 * D1)              W2 = (const float*)d_in[i];
    }
    float* out = (float*)d_out;

    static int smem_set = 0;
    if (!smem_set) {
        cudaFuncSetAttribute(snn_persistent,
                             cudaFuncAttributeMaxDynamicSharedMemorySize, SMEM_BYTES);
        smem_set = 1;
    }

    transpose_W1<<<((D0 + 1) * D1 + 255) / 256, 256>>>(W1);
    transpose_W2<<<((D1 + 1) * D2 + 255) / 256, 256>>>(W2);
    build_xidx<<<T_STEPS * BATCH / 8, 256>>>(x);
    init_misc<<<(BATCH * D2 + 255) / 256, 256>>>(out);
    snn_persistent<<<NBLOCKS, NT, SMEM_BYTES>>>(out);
}

// round 6
// speedup vs baseline: 1.4112x; 1.4112x over previous
#include <cuda_runtime.h>

#define T_STEPS 100
#define BATCH   256
#define D0      784
#define D1      1024
#define D2      256
#define XCAP    128

#define ALPHA 0.8f
#define BETA  0.95f
#define OMB   0.05f

// layer 1: 16 col-chunks of 64 cols (tile 785x64 fl = 200.96 KB), 5 row-groups -> 80 blocks
// layer 2:  8 col-chunks of 32 cols (tile 1025x32 fl = 131.2 KB), 8 row-groups -> 64 blocks
#define N_CH1 16
#define REP1  5
#define NB_L1 (N_CH1 * REP1)      // 80
#define N_CH2 8
#define REP2  8
#define NB_L2 (N_CH2 * REP2)      // 64
#define NBLOCKS (NB_L1 + NB_L2)   // 144  (<= 148 SMs, 1 block/SM, co-resident)
#define NT 1024
#define SMEM_BYTES ((D0 + 1) * 64 * 4)   // 200960 B

// ---------------- device scratch ----------------
__device__ float g_Wt1[(D0 + 1) * D1];              // [k][j], row D0 = zeros
__device__ float g_Wt2[(D1 + 1) * D2];              // [k][j], row D1 = zeros
__device__ unsigned short g_xidx[T_STEPS * BATCH * XCAP];
__device__ int g_xnnz[T_STEPS * BATCH];
__device__ unsigned g_s1mask[T_STEPS][BATCH][32];   // full history: no write hazard, no barrier
__device__ int g_done[T_STEPS];                     // # layer-1 blocks finished step t

// ---------------- prep kernels ----------------
__global__ void transpose_W1(const float* __restrict__ W1) {
    int idx = blockIdx.x * blockDim.x + threadIdx.x;
    if (idx < (D0 + 1) * D1) {
        int k = idx / D1, j = idx % D1;
        g_Wt1[idx] = (k < D0) ? W1[j * D0 + k] : 0.0f;
    }
}
__global__ void transpose_W2(const float* __restrict__ W2) {
    int idx = blockIdx.x * blockDim.x + threadIdx.x;
    if (idx < (D1 + 1) * D2) {
        int k = idx / D2, j = idx % D2;
        g_Wt2[idx] = (k < D1) ? W2[j * D1 + k] : 0.0f;
    }
}
// one warp per (t,b) row; ascending index compaction
__global__ void build_xidx(const float* __restrict__ x) {
    int row  = blockIdx.x * 8 + (threadIdx.x >> 5);
    int lane = threadIdx.x & 31;
    const float* xr = x + (size_t)row * D0;
    unsigned short* out = g_xidx + row * XCAP;
    int base = 0;
    #pragma unroll 1
    for (int c = 0; c < 25; ++c) {
        int i = c * 32 + lane;
        bool p = (i < D0) && (xr[i] != 0.0f);
        unsigned m = __ballot_sync(0xffffffffu, p);
        if (p) {
            int pos = base + __popc(m & ((1u << lane) - 1u));
            if (pos < XCAP) out[pos] = (unsigned short)i;
        }
        base += __popc(m);
    }
    if (lane == 0) {
        if (base > XCAP) base = XCAP;
        int nnzp = (base + 3) & ~3;          // pad to multiple of 4 with zero-row index
        if (nnzp > XCAP) nnzp = XCAP;
        for (int p = base; p < nnzp; ++p) out[p] = (unsigned short)D0;
        g_xnnz[row] = nnzp;
    }
}
__global__ void init_misc(float* __restrict__ out) {
    int i = blockIdx.x * blockDim.x + threadIdx.x;
    if (i < BATCH * D2) out[i] = 0.0f;                     // spikes[t=0] = 0
    if (i < BATCH * 32) ((unsigned*)g_s1mask)[i] = 0u;     // s1 masks at t=0
    if (i < T_STEPS) g_done[i] = (i == 0) ? NB_L1 : 0;     // step 0 "already produced"
}

// bit-expand a 16-bit value to even bit positions of a 32-bit value
__device__ __forceinline__ unsigned expand16(unsigned v) {
    v &= 0xFFFFu;
    v = (v | (v << 8)) & 0x00FF00FFu;
    v = (v | (v << 4)) & 0x0F0F0F0Fu;
    v = (v | (v << 2)) & 0x33333333u;
    v = (v | (v << 1)) & 0x55555555u;
    return v;
}

// ---------------- persistent SNN kernel (flag-synced, no grid barrier) ----------------
__global__ void __launch_bounds__(NT, 1)
snn_persistent(float* __restrict__ out) {
    extern __shared__ float tile[];
    const unsigned FULL = 0xffffffffu;
    int tid  = threadIdx.x;
    int warp = tid >> 5;
    int lane = tid & 31;
    int bx   = blockIdx.x;

    if (bx < NB_L1) {
        // ===== layer 1 (producer, free-running): chunk of 64 cols in SMEM =====
        int ch  = bx & (N_CH1 - 1);
        int rep = bx >> 4;
        int jb  = ch * 64;
        for (int k = warp; k < D0 + 1; k += 32) {
            tile[k * 64 + lane]      = g_Wt1[k * D1 + jb + lane];
            tile[k * 64 + 32 + lane] = g_Wt1[k * D1 + jb + 32 + lane];
        }
        int r0 = (rep * BATCH) / REP1, r1 = ((rep + 1) * BATCH) / REP1;
        int rowA = r0 + warp;
        int rowB = r0 + 32 + warp;
        bool hasA = rowA < r1, hasB = rowB < r1;
        float2 Ia = {0.f, 0.f}, Va = {0.f, 0.f};
        float2 Ib = {0.f, 0.f}, Vb = {0.f, 0.f};
        __syncthreads();

        #pragma unroll 1
        for (int t = 1; t < T_STEPS; ++t) {
            #pragma unroll 1
            for (int pass = 0; pass < 2; ++pass) {
                bool has = pass ? hasB : hasA;
                if (!has) continue;
                int row = pass ? rowB : rowA;
                float2 I = pass ? Ib : Ia;
                float2 V = pass ? Vb : Va;

                int xr = (t - 1) * BATCH + row;
                int nnzp = __ldg(&g_xnnz[xr]);
                const unsigned short* lst = g_xidx + xr * XCAP;
                int i0 = lst[lane], i1 = lst[32 + lane];
                int i2 = lst[64 + lane], i3 = lst[96 + lane];

                float2 acc = {0.f, 0.f};
                // lim is always a multiple of 4 (nnzp % 4 == 0) -> manual 4x unroll
                #define GRP(IR, OFF)                                                 \
                {   int lim = nnzp - (OFF);                                          \
                    if (lim > 0) {                                                   \
                        if (lim > 32) lim = 32;                                      \
                        for (int b = 0; b < lim; b += 4) {                           \
                            int k0 = __shfl_sync(FULL, (IR), b);                     \
                            int k1 = __shfl_sync(FULL, (IR), b + 1);                 \
                            int k2 = __shfl_sync(FULL, (IR), b + 2);                 \
                            int k3 = __shfl_sync(FULL, (IR), b + 3);                 \
                            float2 w0 = *(const float2*)(tile + k0 * 64 + lane * 2); \
                            float2 w1 = *(const float2*)(tile + k1 * 64 + lane * 2); \
                            float2 w2 = *(const float2*)(tile + k2 * 64 + lane * 2); \
                            float2 w3 = *(const float2*)(tile + k3 * 64 + lane * 2); \
                            acc.x += w0.x; acc.y += w0.y;                            \
                            acc.x += w1.x; acc.y += w1.y;                            \
                            acc.x += w2.x; acc.y += w2.y;                            \
                            acc.x += w3.x; acc.y += w3.y;                            \
                        }                                                            \
                    }                                                                \
                }
                GRP(i0, 0) GRP(i1, 32) GRP(i2, 64) GRP(i3, 96)
                #undef GRP

                I.x = ALPHA * I.x + acc.x;  I.y = ALPHA * I.y + acc.y;
                float2 Vp;
                Vp.x = BETA * V.x + OMB * I.x;  Vp.y = BETA * V.y + OMB * I.y;
                bool s0 = Vp.x > 1.0f, s1 = Vp.y > 1.0f;
                V.x = s0 ? 0.f : Vp.x;  V.y = s1 ? 0.f : Vp.y;

                unsigned be = __ballot_sync(FULL, s0);   // cols jb + 2*lane
                unsigned bo = __ballot_sync(FULL, s1);   // cols jb + 2*lane + 1
                if (lane == 0) {
                    unsigned w0 = expand16(be) | (expand16(bo) << 1);
                    unsigned w1 = expand16(be >> 16) | (expand16(bo >> 16) << 1);
                    unsigned long long pk = (unsigned long long)w0 |
                                            ((unsigned long long)w1 << 32);
                    *(unsigned long long*)&g_s1mask[t][row][2 * ch] = pk;
                }
                if (pass) { Ib = I; Vb = V; } else { Ia = I; Va = V; }
            }
            // publish step t: all warps of this block done writing masks
            __syncthreads();
            if (tid == 0) {
                __threadfence();
                atomicAdd(&g_done[t], 1);
            }
        }
    } else {
        // ===== layer 2 (consumer): chunk of 32 cols in SMEM, warp = one batch row =====
        int bi  = bx - NB_L1;
        int ch  = bi & (N_CH2 - 1);
        int rep = bi >> 3;
        int jb  = ch * 32;
        for (int k = warp; k < D1 + 1; k += 32)
            tile[k * 32 + lane] = g_Wt2[k * D2 + jb + lane];
        int row = rep * 32 + warp;
        float I = 0.f, V = 0.f;
        __syncthreads();

        #pragma unroll 1
        for (int t = 1; t < T_STEPS; ++t) {
            // wait until all layer-1 blocks have published step t-1
            if (tid == 0) {
                volatile int* dp = g_done + (t - 1);
                while (*dp < NB_L1) { }
                __threadfence();
            }
            __syncthreads();

            unsigned m = __ldcg(&g_s1mask[t - 1][row][lane]);
            float acc = 0.f;
            #pragma unroll 1
            for (int w2 = 0; w2 < 32; ++w2) {
                unsigned bits = __shfl_sync(FULL, m, w2);
                while (bits) {
                    int b = __ffs(bits) - 1;
                    bits &= bits - 1;
                    acc += tile[(w2 * 32 + b) * 32 + lane];   // ascending k
                }
            }
            I = ALPHA * I + acc;
            float Vp = BETA * V + OMB * I;
            bool s = Vp > 1.0f;
            V = s ? 0.f : Vp;
            out[t * (BATCH * D2) + row * D2 + jb + lane] = s ? 1.0f : 0.0f;
        }
    }
}

// ---------------- launch ----------------
extern "C" void kernel_launch(void* const* d_in, const int* in_sizes, int n_in,
                              void* d_out, int out_size) {
    const float *x = nullptr, *W1 = nullptr, *W2 = nullptr;
    for (int i = 0; i < n_in; ++i) {
        if      (in_sizes[i] == T_STEPS * BATCH * D0) x  = (const float*)d_in[i];
        else if (in_sizes[i] == D1 * D0)              W1 = (const float*)d_in[i];
        else if (in_sizes[i] == D2 * D1)              W2 = (const float*)d_in[i];
    }
    float* out = (float*)d_out;

    static int smem_set = 0;
    if (!smem_set) {
        cudaFuncSetAttribute(snn_persistent,
                             cudaFuncAttributeMaxDynamicSharedMemorySize, SMEM_BYTES);
        smem_set = 1;
    }

    transpose_W1<<<((D0 + 1) * D1 + 255) / 256, 256>>>(W1);
    transpose_W2<<<((D1 + 1) * D2 + 255) / 256, 256>>>(W2);
    build_xidx<<<T_STEPS * BATCH / 8, 256>>>(x);
    init_misc<<<(BATCH * D2 + 255) / 256, 256>>>(out);
    snn_persistent<<<NBLOCKS, NT, SMEM_BYTES>>>(out);
}

// round 7
// speedup vs baseline: 1.6281x; 1.1537x over previous
#include <cuda_runtime.h>

#define T_STEPS 100
#define BATCH   256
#define D0      784
#define D1      1024
#define D2      256
#define XCAP    128

#define ALPHA 0.8f
#define BETA  0.95f
#define OMB   0.05f

// layer 1: 16 col-chunks of 64 cols, 5 row-groups -> 80 blocks
// layer 2:  8 col-chunks of 32 cols, 8 row-groups -> 64 blocks
#define N_CH1 16
#define REP1  5
#define NB_L1 (N_CH1 * REP1)      // 80
#define N_CH2 8
#define REP2  8
#define NB_L2 (N_CH2 * REP2)      // 64
#define NBLOCKS (NB_L1 + NB_L2)   // 144 <= 148 SMs, 1 block/SM, co-resident
#define NT 1024

// dynamic smem: L1 tile 785*64 fl (200960 B) + 32 warps * 128 ushort idx (8192 B) = 209152
// L2 path uses: 1025*32 fl (131200 B) + 32 warps * 1056 ushort list (67584 B) = 198784
#define SMEM_BYTES ((D0 + 1) * 64 * 4 + 32 * 128 * 2)

// prep block ranges
#define NB_T1 3140   // (785*1024)/256
#define NB_T2 1025   // (1025*256)/256
#define NB_XI 3200   // 25600 rows / 8
#define NB_IN 256
#define NB_PREP (NB_T1 + NB_T2 + NB_XI + NB_IN)

// ---------------- device scratch ----------------
__device__ float g_Wt1[(D0 + 1) * D1];              // [k][j], row D0 = zeros
__device__ float g_Wt2[(D1 + 1) * D2];              // [k][j], row D1 = zeros
__device__ unsigned short g_xidx[T_STEPS * BATCH * XCAP];
__device__ int g_xnnz[T_STEPS * BATCH];
__device__ unsigned g_s1mask[T_STEPS][BATCH][32];   // full history, no write hazard
__device__ int g_done[T_STEPS];                     // # layer-1 blocks finished step t

// ---------------- fused prep kernel ----------------
__global__ void prep_all(const float* __restrict__ x,
                         const float* __restrict__ W1,
                         const float* __restrict__ W2,
                         float* __restrict__ out) {
    int bx = blockIdx.x;
    int tid = threadIdx.x;
    if (bx < NB_T1) {
        int idx = bx * 256 + tid;                    // over (D0+1)*D1
        int k = idx / D1, j = idx % D1;
        g_Wt1[idx] = (k < D0) ? W1[j * D0 + k] : 0.0f;
    } else if (bx < NB_T1 + NB_T2) {
        int idx = (bx - NB_T1) * 256 + tid;          // over (D1+1)*D2
        int k = idx / D2, j = idx % D2;
        g_Wt2[idx] = (k < D1) ? W2[j * D1 + k] : 0.0f;
    } else if (bx < NB_T1 + NB_T2 + NB_XI) {
        int row  = (bx - NB_T1 - NB_T2) * 8 + (tid >> 5);
        int lane = tid & 31;
        const float* xr = x + (size_t)row * D0;
        unsigned short* o = g_xidx + row * XCAP;
        int base = 0;
        #pragma unroll 1
        for (int c = 0; c < 25; ++c) {
            int i = c * 32 + lane;
            bool p = (i < D0) && (xr[i] != 0.0f);
            unsigned m = __ballot_sync(0xffffffffu, p);
            if (p) {
                int pos = base + __popc(m & ((1u << lane) - 1u));
                if (pos < XCAP) o[pos] = (unsigned short)i;
            }
            base += __popc(m);
        }
        if (lane == 0) {
            if (base > XCAP) base = XCAP;
            int nnzp = (base + 3) & ~3;              // pad to mult of 4 with zero-row idx
            if (nnzp > XCAP) nnzp = XCAP;
            for (int p = base; p < nnzp; ++p) o[p] = (unsigned short)D0;
            g_xnnz[row] = nnzp;
        }
    } else {
        int i = (bx - NB_T1 - NB_T2 - NB_XI) * 256 + tid;
        if (i < BATCH * D2) out[i] = 0.0f;                  // spikes[t=0] = 0
        if (i < BATCH * 32) ((unsigned*)g_s1mask)[i] = 0u;  // s1 masks at t=0
        if (i < T_STEPS) g_done[i] = (i == 0) ? NB_L1 : 0;
    }
}

// bit-expand 16-bit value to even bit positions of a 32-bit value
__device__ __forceinline__ unsigned expand16(unsigned v) {
    v &= 0xFFFFu;
    v = (v | (v << 8)) & 0x00FF00FFu;
    v = (v | (v << 4)) & 0x0F0F0F0Fu;
    v = (v | (v << 2)) & 0x33333333u;
    v = (v | (v << 1)) & 0x55555555u;
    return v;
}

// ---------------- persistent SNN kernel (flag-synced) ----------------
__global__ void __launch_bounds__(NT, 1)
snn_persistent(float* __restrict__ out) {
    extern __shared__ float tile[];
    const unsigned FULL = 0xffffffffu;
    int tid  = threadIdx.x;
    int warp = tid >> 5;
    int lane = tid & 31;
    int bx   = blockIdx.x;

    if (bx < NB_L1) {
        // ===== layer 1 (producer, free-running): 64-col chunk in SMEM =====
        int ch  = bx & (N_CH1 - 1);
        int rep = bx >> 4;
        int jb  = ch * 64;
        for (int k = warp; k < D0 + 1; k += 32) {
            tile[k * 64 + lane]      = g_Wt1[k * D1 + jb + lane];
            tile[k * 64 + 32 + lane] = g_Wt1[k * D1 + jb + 32 + lane];
        }
        // per-warp index staging buffer (128 ushorts)
        unsigned short* myidx = (unsigned short*)(tile + (D0 + 1) * 64) + warp * 128;

        int r0 = (rep * BATCH) / REP1, r1 = ((rep + 1) * BATCH) / REP1;
        int rowA = r0 + warp;
        int rowB = r0 + 32 + warp;
        bool hasA = rowA < r1, hasB = rowB < r1;
        float2 Ia = {0.f, 0.f}, Va = {0.f, 0.f};
        float2 Ib = {0.f, 0.f}, Vb = {0.f, 0.f};
        __syncthreads();

        #pragma unroll 1
        for (int t = 1; t < T_STEPS; ++t) {
            #pragma unroll 1
            for (int pass = 0; pass < 2; ++pass) {
                bool has = pass ? hasB : hasA;
                if (!has) continue;
                int row = pass ? rowB : rowA;
                float2 I = pass ? Ib : Ia;
                float2 V = pass ? Vb : Va;

                int xr = (t - 1) * BATCH + row;
                int nnzp = __ldg(&g_xnnz[xr]);
                // stage this row's index list into SMEM (64 uints = 128 ushorts)
                const unsigned* lst = (const unsigned*)(g_xidx + xr * XCAP);
                ((unsigned*)myidx)[lane]      = __ldg(lst + lane);
                ((unsigned*)myidx)[32 + lane] = __ldg(lst + 32 + lane);
                __syncwarp();

                float2 acc = {0.f, 0.f};
                #pragma unroll 1
                for (int i = 0; i < nnzp; i += 4) {       // nnzp % 4 == 0
                    uint2 pp = *(const uint2*)(myidx + i); // 8B broadcast
                    int k0 = pp.x & 0xffff, k1 = pp.x >> 16;
                    int k2 = pp.y & 0xffff, k3 = pp.y >> 16;
                    float2 w0 = *(const float2*)(tile + k0 * 64 + lane * 2);
                    float2 w1 = *(const float2*)(tile + k1 * 64 + lane * 2);
                    float2 w2 = *(const float2*)(tile + k2 * 64 + lane * 2);
                    float2 w3 = *(const float2*)(tile + k3 * 64 + lane * 2);
                    acc.x += w0.x; acc.y += w0.y;
                    acc.x += w1.x; acc.y += w1.y;
                    acc.x += w2.x; acc.y += w2.y;
                    acc.x += w3.x; acc.y += w3.y;
                }

                I.x = ALPHA * I.x + acc.x;  I.y = ALPHA * I.y + acc.y;
                float2 Vp;
                Vp.x = BETA * V.x + OMB * I.x;  Vp.y = BETA * V.y + OMB * I.y;
                bool s0 = Vp.x > 1.0f, s1 = Vp.y > 1.0f;
                V.x = s0 ? 0.f : Vp.x;  V.y = s1 ? 0.f : Vp.y;

                unsigned be = __ballot_sync(FULL, s0);   // cols jb + 2*lane
                unsigned bo = __ballot_sync(FULL, s1);   // cols jb + 2*lane + 1
                if (lane == 0) {
                    unsigned w0m = expand16(be) | (expand16(bo) << 1);
                    unsigned w1m = expand16(be >> 16) | (expand16(bo >> 16) << 1);
                    unsigned long long pk = (unsigned long long)w0m |
                                            ((unsigned long long)w1m << 32);
                    *(unsigned long long*)&g_s1mask[t][row][2 * ch] = pk;
                }
                if (pass) { Ib = I; Vb = V; } else { Ia = I; Va = V; }
            }
            __syncthreads();
            if (tid == 0) {
                __threadfence();
                atomicAdd(&g_done[t], 1);
            }
        }
    } else {
        // ===== layer 2 (consumer): 32-col chunk in SMEM, warp = one batch row =====
        int bi  = bx - NB_L1;
        int ch  = bi & (N_CH2 - 1);
        int rep = bi >> 3;
        int jb  = ch * 32;
        for (int k = warp; k < D1 + 1; k += 32)
            tile[k * 32 + lane] = g_Wt2[k * D2 + jb + lane];
        // per-warp spike index list (cap 1056 ushorts, worst case 1024+pad)
        unsigned short* mylist = (unsigned short*)(tile + (D1 + 1) * 32) + warp * 1056;
        int row = rep * 32 + warp;
        float I = 0.f, V = 0.f;
        __syncthreads();

        #pragma unroll 1
        for (int t = 1; t < T_STEPS; ++t) {
            if (tid == 0) {
                volatile int* dp = g_done + (t - 1);
                while (*dp < NB_L1) { }
                __threadfence();
            }
            __syncthreads();

            // mask -> ascending compact index list in SMEM
            unsigned m = __ldcg(&g_s1mask[t - 1][row][lane]);  // k in [32*lane, 32*lane+32)
            int cnt = __popc(m);
            int incl = cnt;
            #pragma unroll
            for (int o = 1; o < 32; o <<= 1) {
                int v = __shfl_up_sync(FULL, incl, o);
                if (lane >= o) incl += v;
            }
            int base = incl - cnt;
            int total = __shfl_sync(FULL, incl, 31);
            unsigned bits = m;
            int off = base, kb = lane << 5;
            while (bits) {
                int b = __ffs(bits) - 1;
                bits &= bits - 1;
                mylist[off++] = (unsigned short)(kb + b);
            }
            int totp = (total + 3) & ~3;
            if (lane == 31)
                for (int p = total; p < totp; ++p) mylist[p] = (unsigned short)D1; // zero row
            __syncwarp();

            float acc = 0.f;
            #pragma unroll 1
            for (int i = 0; i < totp; i += 4) {
                ushort4 kk = *(const ushort4*)(mylist + i);   // 8B broadcast
                acc += tile[(int)kk.x * 32 + lane];
                acc += tile[(int)kk.y * 32 + lane];
                acc += tile[(int)kk.z * 32 + lane];
                acc += tile[(int)kk.w * 32 + lane];
            }

            I = ALPHA * I + acc;
            float Vp = BETA * V + OMB * I;
            bool s = Vp > 1.0f;
            V = s ? 0.f : Vp;
            out[t * (BATCH * D2) + row * D2 + jb + lane] = s ? 1.0f : 0.0f;
        }
    }
}

// ---------------- launch ----------------
extern "C" void kernel_launch(void* const* d_in, const int* in_sizes, int n_in,
                              void* d_out, int out_size) {
    const float *x = nullptr, *W1 = nullptr, *W2 = nullptr;
    for (int i = 0; i < n_in; ++i) {
        if      (in_sizes[i] == T_STEPS * BATCH * D0) x  = (const float*)d_in[i];
        else if (in_sizes[i] == D1 * D0)              W1 = (const float*)d_in[i];
        else if (in_sizes[i] == D2 * D1)              W2 = (const float*)d_in[i];
    }
    float* out = (float*)d_out;

    static int smem_set = 0;
    if (!smem_set) {
        cudaFuncSetAttribute(snn_persistent,
                             cudaFuncAttributeMaxDynamicSharedMemorySize, SMEM_BYTES);
        smem_set = 1;
    }

    prep_all<<<NB_PREP, 256>>>(x, W1, W2, out);
    snn_persistent<<<NBLOCKS, NT, SMEM_BYTES>>>(out);
}